// round 14
// baseline (speedup 1.0000x reference)
#include <cuda_runtime.h>
#include <cuda_fp16.h>
#include <cstdint>
#include <cstddef>

#define NN 8192
#define DD 256
#define NB 264            // 256 dims + 8 halves pad -> 528B row

// ---------------- device scratch (no runtime alloc allowed) ----------------
__device__ __align__(128) __half g_Wh16[(size_t)NN * NB];
__device__ __align__(128) __half g_X16[(size_t)NN * DD];
__device__ __align__(128) __half g_W16[DD * DD];
__device__ float g_fs[NN], g_fd[NN];
__device__ float g_ws[DD], g_wd[DD];
__device__ unsigned g_R2[NN];        // half2(R_i, R_i),  R = exp(-0.8 fs)
__device__ unsigned g_B2[NN / 2];    // half2(B_2j, B_2j+1), B = exp(fd)
__device__ unsigned g_D2[NN / 2];    // half2(D_2j, D_2j+1), D = exp(0.2 fd)

// ---------------- helpers ----------------
__device__ __forceinline__ uint32_t smem_u32(const void* p) {
    uint32_t a;
    asm("{ .reg .u64 t; cvta.to.shared.u64 t, %1; cvt.u32.u64 %0, t; }" : "=r"(a) : "l"(p));
    return a;
}
__device__ __forceinline__ __half2 u2h2(unsigned u) { return *reinterpret_cast<__half2*>(&u); }
__device__ __forceinline__ unsigned h22u(__half2 h) { return *reinterpret_cast<unsigned*>(&h); }

#define CP16(dst, src)   asm volatile("cp.async.cg.shared.global [%0], [%1], 16;" :: "r"(dst), "l"(src))
#define CPCOMMIT()       asm volatile("cp.async.commit_group;" ::: "memory")
#define CPWAIT0()        asm volatile("cp.async.wait_group 0;" ::: "memory")
#define MBAR_INIT(mb, c) asm volatile("mbarrier.init.shared.b64 [%0], %1;" :: "r"(mb), "r"(c) : "memory")
#define MBAR_ARRIVE(mb)  asm volatile("mbarrier.arrive.shared.b64 _, [%0];" :: "r"(mb) : "memory")
#define EXPECT_TX(mb, n) asm volatile("mbarrier.arrive.expect_tx.shared.b64 _, [%0], %1;" :: "r"(mb), "r"(n) : "memory")
#define TMA_BULK(dst, src, bytes, mb) \
    asm volatile("cp.async.bulk.shared::cluster.global.mbarrier::complete_tx::bytes [%0], [%1], %2, [%3];" \
                 :: "r"(dst), "l"(src), "r"(bytes), "r"(mb) : "memory")

__device__ __forceinline__ void mbar_wait(uint32_t mb, uint32_t parity) {
    uint32_t done;
    asm volatile(
        "{\n\t.reg .pred p;\n\t"
        "mbarrier.try_wait.parity.shared.b64 p, [%1], %2, 0x989680;\n\t"
        "selp.b32 %0, 1, 0, p;\n\t}"
        : "=r"(done) : "r"(mb), "r"(parity) : "memory");
    if (!done) {
        asm volatile(
            "{\n\t.reg .pred P1;\n\t"
            "WL_%=:\n\t"
            "mbarrier.try_wait.parity.shared.b64 P1, [%0], %1, 0x989680;\n\t"
            "@P1 bra.uni WD_%=;\n\t"
            "bra.uni WL_%=;\n\t"
            "WD_%=:\n\t}"
            :: "r"(mb), "r"(parity) : "memory");
    }
}

__device__ __forceinline__ void ldsm4(unsigned &r0, unsigned &r1, unsigned &r2, unsigned &r3,
                                      uint32_t addr) {
    asm volatile("ldmatrix.sync.aligned.m8n8.x4.shared.b16 {%0,%1,%2,%3}, [%4];"
                 : "=r"(r0), "=r"(r1), "=r"(r2), "=r"(r3) : "r"(addr));
}
__device__ __forceinline__ void ldsm4t(unsigned &r0, unsigned &r1, unsigned &r2, unsigned &r3,
                                       uint32_t addr) {
    asm volatile("ldmatrix.sync.aligned.m8n8.x4.trans.shared.b16 {%0,%1,%2,%3}, [%4];"
                 : "=r"(r0), "=r"(r1), "=r"(r2), "=r"(r3) : "r"(addr));
}
__device__ __forceinline__ void mma16816(float* c, unsigned a0, unsigned a1, unsigned a2,
                                         unsigned a3, unsigned b0, unsigned b1) {
    asm volatile(
        "mma.sync.aligned.m16n8k16.row.col.f32.f16.f16.f32 "
        "{%0,%1,%2,%3}, {%4,%5,%6,%7}, {%8,%9}, {%0,%1,%2,%3};"
        : "+f"(c[0]), "+f"(c[1]), "+f"(c[2]), "+f"(c[3])
        : "r"(a0), "r"(a1), "r"(a2), "r"(a3), "r"(b0), "r"(b1));
}

// ---------------------------------------------------------------------------
// K0: convert X (blocks 0..1023), W (1024..1055), wvec (block 1056)
// ---------------------------------------------------------------------------
__global__ void conv_xw_wvec_kernel(const float* __restrict__ X, const float* __restrict__ W,
                                    const float* __restrict__ a_src,
                                    const float* __restrict__ a_dst) {
    if (blockIdx.x < 1024) {
        size_t i = ((size_t)blockIdx.x * 256 + threadIdx.x) * 8;
        float4 v0 = *(const float4*)&X[i];
        float4 v1 = *(const float4*)&X[i + 4];
        uint4 o;
        o.x = h22u(__floats2half2_rn(v0.x, v0.y));
        o.y = h22u(__floats2half2_rn(v0.z, v0.w));
        o.z = h22u(__floats2half2_rn(v1.x, v1.y));
        o.w = h22u(__floats2half2_rn(v1.z, v1.w));
        *(uint4*)&g_X16[i] = o;
    } else if (blockIdx.x < 1056) {
        size_t i = ((size_t)(blockIdx.x - 1024) * 256 + threadIdx.x) * 8;
        float4 v0 = *(const float4*)&W[i];
        float4 v1 = *(const float4*)&W[i + 4];
        uint4 o;
        o.x = h22u(__floats2half2_rn(v0.x, v0.y));
        o.y = h22u(__floats2half2_rn(v0.z, v0.w));
        o.z = h22u(__floats2half2_rn(v1.x, v1.y));
        o.w = h22u(__floats2half2_rn(v1.z, v1.w));
        *(uint4*)&g_W16[i] = o;
    } else {
        int i = threadIdx.x;
        float s = 0.f, t = 0.f;
        const float4* wr = (const float4*)&W[(size_t)i * DD];
#pragma unroll 8
        for (int o = 0; o < DD / 4; o++) {
            float4 w = wr[o];
            float4 as = *(const float4*)&a_src[o * 4];
            float4 ad = *(const float4*)&a_dst[o * 4];
            s += w.x * as.x + w.y * as.y + w.z * as.z + w.w * as.w;
            t += w.x * ad.x + w.y * ad.y + w.z * ad.z + w.w * ad.w;
        }
        g_ws[i] = s;
        g_wd[i] = t;
    }
}

// ---------------------------------------------------------------------------
// K1: fs/fd (warp per row) + fused consts epilogue (R2/B2/D2)
// ---------------------------------------------------------------------------
__global__ __launch_bounds__(256) void fsfd_consts_kernel(const float* __restrict__ X) {
    __shared__ float fd8[8];
    const int warp = threadIdx.x >> 5, lane = threadIdx.x & 31;
    const int row = blockIdx.x * 8 + warp;
    const float* xr = &X[(size_t)row * DD];
    float s = 0.f, t = 0.f;
#pragma unroll
    for (int k = lane; k < DD; k += 32) {
        float x = xr[k];
        s += x * g_ws[k];
        t += x * g_wd[k];
    }
#pragma unroll
    for (int o = 16; o > 0; o >>= 1) {
        s += __shfl_xor_sync(0xffffffffu, s, o);
        t += __shfl_xor_sync(0xffffffffu, t, o);
    }
    if (lane == 0) {
        g_fs[row] = s;
        g_fd[row] = t;
        __half r = __float2half_rn(__expf(-0.8f * s));
        g_R2[row] = h22u(__halves2half2(r, r));
        fd8[warp] = t;
    }
    __syncthreads();
    if (threadIdx.x < 4) {
        float f0 = fd8[2 * threadIdx.x], f1 = fd8[2 * threadIdx.x + 1];
        int j = blockIdx.x * 4 + threadIdx.x;
        g_B2[j] = h22u(__floats2half2_rn(__expf(f0), __expf(f1)));
        g_D2[j] = h22u(__floats2half2_rn(__expf(0.2f * f0), __expf(0.2f * f1)));
    }
}

// ---------------------------------------------------------------------------
// K2: Wh16 = X16 @ W16  via mma.sync + cp.async tiles
// ---------------------------------------------------------------------------
__global__ __launch_bounds__(256) void wh_gemm_kernel() {
    __shared__ __align__(16) __half Xs[64 * 72];
    __shared__ __align__(16) __half Wsm[64 * 264];
    const int tid = threadIdx.x;
    const int warp = tid >> 5, lane = tid & 31;
    const int wm = warp >> 2, wn = warp & 3;
    const int row0 = blockIdx.x * 64;

    float c[2][8][4];
#pragma unroll
    for (int a = 0; a < 2; a++)
#pragma unroll
        for (int b = 0; b < 8; b++)
#pragma unroll
            for (int d = 0; d < 4; d++) c[a][b][d] = 0.f;

    for (int kt = 0; kt < 4; kt++) {
#pragma unroll
        for (int i = 0; i < 2; i++) {
            int ci = i * 256 + tid;
            int r = ci >> 3, o = ci & 7;
            CP16(smem_u32(&Xs[r * 72 + o * 8]),
                 &g_X16[(size_t)(row0 + r) * DD + kt * 64 + o * 8]);
        }
#pragma unroll
        for (int i = 0; i < 8; i++) {
            int ci = i * 256 + tid;
            int r = ci >> 5, o = ci & 31;
            CP16(smem_u32(&Wsm[r * 264 + o * 8]),
                 &g_W16[(size_t)(kt * 64 + r) * DD + o * 8]);
        }
        CPCOMMIT();
        CPWAIT0();
        __syncthreads();

#pragma unroll
        for (int ks = 0; ks < 4; ks++) {
            unsigned a[2][4];
#pragma unroll
            for (int mt = 0; mt < 2; mt++)
                ldsm4(a[mt][0], a[mt][1], a[mt][2], a[mt][3],
                      smem_u32(&Xs[(wm * 32 + mt * 16 + (lane & 15)) * 72 +
                                   ks * 16 + ((lane >> 4) << 3)]));
#pragma unroll
            for (int np = 0; np < 4; np++) {
                unsigned b0, b1, b2, b3;
                ldsm4t(b0, b1, b2, b3,
                       smem_u32(&Wsm[(ks * 16 + (lane & 15)) * 264 +
                                     wn * 64 + np * 16 + ((lane >> 4) << 3)]));
#pragma unroll
                for (int mt = 0; mt < 2; mt++) {
                    mma16816(c[mt][np * 2], a[mt][0], a[mt][1], a[mt][2], a[mt][3], b0, b1);
                    mma16816(c[mt][np * 2 + 1], a[mt][0], a[mt][1], a[mt][2], a[mt][3], b2, b3);
                }
            }
        }
        __syncthreads();
    }

    const int g = lane >> 2, tq = lane & 3;
#pragma unroll
    for (int mt = 0; mt < 2; mt++)
#pragma unroll
        for (int nb = 0; nb < 8; nb++) {
            int row = row0 + wm * 32 + mt * 16 + g;
            int col = wn * 64 + nb * 8 + tq * 2;
            *(unsigned*)&g_Wh16[(size_t)row * NB + col] =
                h22u(__floats2half2_rn(c[mt][nb][0], c[mt][nb][1]));
            *(unsigned*)&g_Wh16[(size_t)(row + 8) * NB + col] =
                h22u(__floats2half2_rn(c[mt][nb][2], c[mt][nb][3]));
        }
}

// ---------------------------------------------------------------------------
// K3: warp-specialized fused attn, 2 CTAs/SM.
// 256 CTAs x 32 rows, 320 threads: warps 0-7 = MMA (m32n32, B loaded once),
// warps 8-9 = producers (64 thr). BK=64 -> 128 tiles. P depth 3, B depth 2.
// ---------------------------------------------------------------------------
#define ROWS 32
#define BK 64
#define NT (NN / BK)                   // 128 tiles
#define PFB(s) (0 + 8 * (s))           // 3 stages
#define PEB(s) (24 + 8 * (s))
#define BFB(s) (48 + 8 * (s))          // 2 stages
#define BEB(s) (64 + 8 * (s))
#define L4O 128
#define PSO 1024
#define PS_B 4608                      // 32 * 72 halves * 2B
#define BS0O (PSO + 3 * PS_B)          // 14848
#define BS_B 33792                     // 64 * 264 halves * 2B
#define K3_SMEM (BS0O + 2 * BS_B)      // 82432
#define BTILE 33792u

__global__ __launch_bounds__(320, 2) void attn_kernel(const int* __restrict__ adj,
                                                      float* __restrict__ out) {
    extern __shared__ __align__(128) char sm[];
    const uint32_t base = smem_u32(sm);
    float* l4 = (float*)(sm + L4O);    // [32][2]

    const int tid = threadIdx.x;
    const int warp = tid >> 5, lane = tid & 31;
    const int row0 = blockIdx.x * ROWS;

    if (tid == 0) {
#pragma unroll
        for (int s = 0; s < 3; s++) {
            MBAR_INIT(base + PFB(s), 64);
            MBAR_INIT(base + PEB(s), 256);
        }
#pragma unroll
        for (int s = 0; s < 2; s++) {
            MBAR_INIT(base + BFB(s), 1);
            MBAR_INIT(base + BEB(s), 256);
        }
    }
    __syncthreads();

    if (warp >= 8) {
        // ================= PRODUCER warps (64 threads) =================
        const int ptid = tid - 256;
        const int r = ptid >> 1, h = ptid & 1;       // row (0..31), 32-col half
        const __half2 R2h = u2h2(g_R2[row0 + r]);
        const int4* arow = (const int4*)(adj + (size_t)(row0 + r) * NN);
        float lacc = 0.f;
        int be_ph0 = 0, be_ph1 = 0;

        if (ptid == 0) {
            EXPECT_TX(base + BFB(0), BTILE);
            TMA_BULK(base + BS0O, (const void*)&g_Wh16[0], BTILE, base + BFB(0));
        }

        for (int t = 0; t < NT; t++) {
            const int u = t / 3;
            const int s = t - 3 * u;
            __half* Ps = (__half*)(sm + PSO + s * PS_B);

            // TMA for tile t+1 into B stage (t+1)&1
            if (ptid == 0 && t + 1 < NT) {
                const int b2 = (t + 1) & 1;
                if (t + 1 >= 2) {
                    if (b2 == 0) { mbar_wait(base + BEB(0), be_ph0); be_ph0 ^= 1; }
                    else         { mbar_wait(base + BEB(1), be_ph1); be_ph1 ^= 1; }
                }
                EXPECT_TX(base + BFB(b2), BTILE);
                TMA_BULK(base + BS0O + b2 * BS_B,
                         (const void*)&g_Wh16[(size_t)(t + 1) * BK * NB], BTILE,
                         base + BFB(b2));
            }

            // wait until MMA released this P stage (tile t-3 consumed)
            if (t >= 3) mbar_wait(base + PEB(s), (u - 1) & 1);

            // edge-gen: 32 cols for (r, h)
            const int cb = t * BK + h * 32;
            const int hb = cb >> 1;
            uint4 bu[4], du[4];
#pragma unroll
            for (int i = 0; i < 4; i++) {
                bu[i] = *(const uint4*)&g_B2[hb + i * 4];
                du[i] = *(const uint4*)&g_D2[hb + i * 4];
            }
            const unsigned* bb = (const unsigned*)bu;
            const unsigned* dd = (const unsigned*)du;
            int4 a4[8];
#pragma unroll
            for (int u2 = 0; u2 < 8; u2++) a4[u2] = __ldcs(&arow[cb / 4 + u2]);
#pragma unroll
            for (int u2 = 0; u2 < 8; u2++) {
                unsigned mka = (a4[u2].x > 0 ? 0x3C00u : 0u) | (a4[u2].y > 0 ? 0x3C000000u : 0u);
                unsigned mkb = (a4[u2].z > 0 ? 0x3C00u : 0u) | (a4[u2].w > 0 ? 0x3C000000u : 0u);
                __half2 pa = __hmul2(__hmax2(u2h2(bb[u2 * 2]), __hmul2(R2h, u2h2(dd[u2 * 2]))),
                                     u2h2(mka));
                __half2 pb = __hmul2(__hmax2(u2h2(bb[u2 * 2 + 1]),
                                             __hmul2(R2h, u2h2(dd[u2 * 2 + 1]))),
                                     u2h2(mkb));
                *(uint2*)&Ps[r * 72 + h * 32 + u2 * 4] = make_uint2(h22u(pa), h22u(pb));
                float2 fa = __half22float2(__hadd2(pa, pb));
                lacc += fa.x + fa.y;
            }
            MBAR_ARRIVE(base + PFB(s));
        }
        l4[r * 2 + h] = lacc;
        __syncthreads();   // join with consumers
    } else {
        // ================= MMA warps (256 threads, m32 x n32 each) ==========
        const int wn = warp;                       // 0..7 -> col base wn*32
        const int alo = lane & 15, ahi = (lane >> 4) << 3;
        int bf_ph0 = 0, bf_ph1 = 0;

        float c[2][4][4];
#pragma unroll
        for (int a = 0; a < 2; a++)
#pragma unroll
            for (int b = 0; b < 4; b++)
#pragma unroll
                for (int d = 0; d < 4; d++) c[a][b][d] = 0.f;

        for (int t = 0; t < NT; t++) {
            const int u = t / 3;
            const int s = t - 3 * u;
            const int b = t & 1;
            const __half* Ps = (const __half*)(sm + PSO + s * PS_B);
            const __half* Bs = (const __half*)(sm + BS0O + b * BS_B);

            mbar_wait(base + PFB(s), u & 1);
            if (b == 0) { mbar_wait(base + BFB(0), bf_ph0); bf_ph0 ^= 1; }
            else        { mbar_wait(base + BFB(1), bf_ph1); bf_ph1 ^= 1; }

#pragma unroll
            for (int ks = 0; ks < 4; ks++) {
                unsigned a[2][4];
#pragma unroll
                for (int mt = 0; mt < 2; mt++)
                    ldsm4(a[mt][0], a[mt][1], a[mt][2], a[mt][3],
                          smem_u32(&Ps[(mt * 16 + alo) * 72 + ks * 16 + ahi]));
#pragma unroll
                for (int np = 0; np < 2; np++) {
                    unsigned b0, b1, b2, b3;
                    ldsm4t(b0, b1, b2, b3,
                           smem_u32(&Bs[(ks * 16 + alo) * 264 + wn * 32 + np * 16 + ahi]));
#pragma unroll
                    for (int mt = 0; mt < 2; mt++) {
                        mma16816(c[mt][np * 2], a[mt][0], a[mt][1], a[mt][2], a[mt][3], b0, b1);
                        mma16816(c[mt][np * 2 + 1], a[mt][0], a[mt][1], a[mt][2], a[mt][3], b2, b3);
                    }
                }
            }
            MBAR_ARRIVE(base + PEB(s));
            MBAR_ARRIVE(base + BEB(b));
        }

        __syncthreads();   // l4 ready

        // ---- epilogue: normalize + elu + store (rows all 32, cols wn*32+32) ----
#pragma unroll
        for (int mt = 0; mt < 2; mt++) {
            int rl = mt * 16 + (lane >> 2);
            float inv1 = 1.f / (l4[rl * 2] + l4[rl * 2 + 1]);
            float inv2 = 1.f / (l4[(rl + 8) * 2] + l4[(rl + 8) * 2 + 1]);
#pragma unroll
            for (int nb = 0; nb < 4; nb++) {
                int col = wn * 32 + nb * 8 + (lane & 3) * 2;
                float x0 = c[mt][nb][0] * inv1, x1 = c[mt][nb][1] * inv1;
                float y0 = c[mt][nb][2] * inv2, y1 = c[mt][nb][3] * inv2;
                float2 v1 = make_float2(x0 > 0.f ? x0 : expm1f(x0),
                                        x1 > 0.f ? x1 : expm1f(x1));
                float2 v2 = make_float2(y0 > 0.f ? y0 : expm1f(y0),
                                        y1 > 0.f ? y1 : expm1f(y1));
                *(float2*)&out[(size_t)(row0 + rl) * DD + col] = v1;
                *(float2*)&out[(size_t)(row0 + rl + 8) * DD + col] = v2;
            }
        }
    }
}

// ---------------------------------------------------------------------------
extern "C" void kernel_launch(void* const* d_in, const int* in_sizes, int n_in,
                              void* d_out, int out_size) {
    const float* X     = (const float*)d_in[0];
    const int*   adj   = (const int*)d_in[1];
    const float* W     = (const float*)d_in[2];
    const float* a_src = (const float*)d_in[3];
    const float* a_dst = (const float*)d_in[4];
    float* out = (float*)d_out;
    (void)in_sizes; (void)n_in; (void)out_size;

    cudaFuncSetAttribute(attn_kernel,
                         cudaFuncAttributeMaxDynamicSharedMemorySize, K3_SMEM);

    conv_xw_wvec_kernel<<<1057, 256>>>(X, W, a_src, a_dst);
    fsfd_consts_kernel<<<NN / 8, 256>>>(X);
    wh_gemm_kernel<<<NN / 64, 256>>>();
    attn_kernel<<<NN / ROWS, 320, K3_SMEM>>>(adj, out);
}

// round 15
// speedup vs baseline: 1.4221x; 1.4221x over previous
#include <cuda_runtime.h>
#include <cuda_fp16.h>
#include <cstdint>
#include <cstddef>

#define NN 8192
#define DD 256
#define NB 264            // 256 dims + 8 halves pad -> 528B row

// ---------------- device scratch (no runtime alloc allowed) ----------------
__device__ __align__(128) __half g_Wh16[(size_t)NN * NB];
__device__ __align__(128) __half g_X16[(size_t)NN * DD];
__device__ __align__(128) __half g_W16[DD * DD];
__device__ float g_fs[NN], g_fd[NN];
__device__ float g_ws[DD], g_wd[DD];
__device__ unsigned g_R2[NN];        // half2(R_i, R_i),  R = exp(-0.8 fs)
__device__ unsigned g_B2[NN / 2];    // half2(B_2j, B_2j+1), B = exp(fd)
__device__ unsigned g_D2[NN / 2];    // half2(D_2j, D_2j+1), D = exp(0.2 fd)

// ---------------- helpers ----------------
__device__ __forceinline__ uint32_t smem_u32(const void* p) {
    uint32_t a;
    asm("{ .reg .u64 t; cvta.to.shared.u64 t, %1; cvt.u32.u64 %0, t; }" : "=r"(a) : "l"(p));
    return a;
}
__device__ __forceinline__ __half2 u2h2(unsigned u) { return *reinterpret_cast<__half2*>(&u); }
__device__ __forceinline__ unsigned h22u(__half2 h) { return *reinterpret_cast<unsigned*>(&h); }

#define CP16(dst, src)   asm volatile("cp.async.cg.shared.global [%0], [%1], 16;" :: "r"(dst), "l"(src))
#define CPCOMMIT()       asm volatile("cp.async.commit_group;" ::: "memory")
#define CPWAIT0()        asm volatile("cp.async.wait_group 0;" ::: "memory")
#define MBAR_INIT(mb, c) asm volatile("mbarrier.init.shared.b64 [%0], %1;" :: "r"(mb), "r"(c) : "memory")
#define MBAR_ARRIVE(mb)  asm volatile("mbarrier.arrive.shared.b64 _, [%0];" :: "r"(mb) : "memory")
#define EXPECT_TX(mb, n) asm volatile("mbarrier.arrive.expect_tx.shared.b64 _, [%0], %1;" :: "r"(mb), "r"(n) : "memory")
#define TMA_BULK(dst, src, bytes, mb) \
    asm volatile("cp.async.bulk.shared::cluster.global.mbarrier::complete_tx::bytes [%0], [%1], %2, [%3];" \
                 :: "r"(dst), "l"(src), "r"(bytes), "r"(mb) : "memory")

__device__ __forceinline__ void mbar_wait(uint32_t mb, uint32_t parity) {
    uint32_t done;
    asm volatile(
        "{\n\t.reg .pred p;\n\t"
        "mbarrier.try_wait.parity.shared.b64 p, [%1], %2;\n\t"
        "selp.b32 %0, 1, 0, p;\n\t}"
        : "=r"(done) : "r"(mb), "r"(parity) : "memory");
    if (!done) {
        asm volatile(
            "{\n\t.reg .pred P1;\n\t"
            "WL_%=:\n\t"
            "mbarrier.try_wait.parity.shared.b64 P1, [%0], %1;\n\t"
            "@P1 bra.uni WD_%=;\n\t"
            "bra.uni WL_%=;\n\t"
            "WD_%=:\n\t}"
            :: "r"(mb), "r"(parity) : "memory");
    }
}

__device__ __forceinline__ void ldsm4(unsigned &r0, unsigned &r1, unsigned &r2, unsigned &r3,
                                      uint32_t addr) {
    asm volatile("ldmatrix.sync.aligned.m8n8.x4.shared.b16 {%0,%1,%2,%3}, [%4];"
                 : "=r"(r0), "=r"(r1), "=r"(r2), "=r"(r3) : "r"(addr));
}
__device__ __forceinline__ void ldsm4t(unsigned &r0, unsigned &r1, unsigned &r2, unsigned &r3,
                                       uint32_t addr) {
    asm volatile("ldmatrix.sync.aligned.m8n8.x4.trans.shared.b16 {%0,%1,%2,%3}, [%4];"
                 : "=r"(r0), "=r"(r1), "=r"(r2), "=r"(r3) : "r"(addr));
}
// fp32-acc mma (used in wh_gemm)
__device__ __forceinline__ void mma16816(float* c, unsigned a0, unsigned a1, unsigned a2,
                                         unsigned a3, unsigned b0, unsigned b1) {
    asm volatile(
        "mma.sync.aligned.m16n8k16.row.col.f32.f16.f16.f32 "
        "{%0,%1,%2,%3}, {%4,%5,%6,%7}, {%8,%9}, {%0,%1,%2,%3};"
        : "+f"(c[0]), "+f"(c[1]), "+f"(c[2]), "+f"(c[3])
        : "r"(a0), "r"(a1), "r"(a2), "r"(a3), "r"(b0), "r"(b1));
}
// fp16-acc mma (2x rate) -- used in attn
__device__ __forceinline__ void mma16816h(unsigned &c0, unsigned &c1, unsigned a0, unsigned a1,
                                          unsigned a2, unsigned a3, unsigned b0, unsigned b1) {
    asm volatile(
        "mma.sync.aligned.m16n8k16.row.col.f16.f16.f16.f16 "
        "{%0,%1}, {%2,%3,%4,%5}, {%6,%7}, {%0,%1};"
        : "+r"(c0), "+r"(c1)
        : "r"(a0), "r"(a1), "r"(a2), "r"(a3), "r"(b0), "r"(b1));
}

// ---------------------------------------------------------------------------
// K0: convert X (blocks 0..1023), W (1024..1055), wvec (block 1056)
// ---------------------------------------------------------------------------
__global__ void conv_xw_wvec_kernel(const float* __restrict__ X, const float* __restrict__ W,
                                    const float* __restrict__ a_src,
                                    const float* __restrict__ a_dst) {
    if (blockIdx.x < 1024) {
        size_t i = ((size_t)blockIdx.x * 256 + threadIdx.x) * 8;
        float4 v0 = *(const float4*)&X[i];
        float4 v1 = *(const float4*)&X[i + 4];
        uint4 o;
        o.x = h22u(__floats2half2_rn(v0.x, v0.y));
        o.y = h22u(__floats2half2_rn(v0.z, v0.w));
        o.z = h22u(__floats2half2_rn(v1.x, v1.y));
        o.w = h22u(__floats2half2_rn(v1.z, v1.w));
        *(uint4*)&g_X16[i] = o;
    } else if (blockIdx.x < 1056) {
        size_t i = ((size_t)(blockIdx.x - 1024) * 256 + threadIdx.x) * 8;
        float4 v0 = *(const float4*)&W[i];
        float4 v1 = *(const float4*)&W[i + 4];
        uint4 o;
        o.x = h22u(__floats2half2_rn(v0.x, v0.y));
        o.y = h22u(__floats2half2_rn(v0.z, v0.w));
        o.z = h22u(__floats2half2_rn(v1.x, v1.y));
        o.w = h22u(__floats2half2_rn(v1.z, v1.w));
        *(uint4*)&g_W16[i] = o;
    } else {
        int i = threadIdx.x;
        float s = 0.f, t = 0.f;
        const float4* wr = (const float4*)&W[(size_t)i * DD];
#pragma unroll 8
        for (int o = 0; o < DD / 4; o++) {
            float4 w = wr[o];
            float4 as = *(const float4*)&a_src[o * 4];
            float4 ad = *(const float4*)&a_dst[o * 4];
            s += w.x * as.x + w.y * as.y + w.z * as.z + w.w * as.w;
            t += w.x * ad.x + w.y * ad.y + w.z * ad.z + w.w * ad.w;
        }
        g_ws[i] = s;
        g_wd[i] = t;
    }
}

// ---------------------------------------------------------------------------
// K1: fs/fd (warp per row) + fused consts epilogue (R2/B2/D2)
// ---------------------------------------------------------------------------
__global__ __launch_bounds__(256) void fsfd_consts_kernel(const float* __restrict__ X) {
    __shared__ float fd8[8];
    const int warp = threadIdx.x >> 5, lane = threadIdx.x & 31;
    const int row = blockIdx.x * 8 + warp;
    const float* xr = &X[(size_t)row * DD];
    float s = 0.f, t = 0.f;
#pragma unroll
    for (int k = lane; k < DD; k += 32) {
        float x = xr[k];
        s += x * g_ws[k];
        t += x * g_wd[k];
    }
#pragma unroll
    for (int o = 16; o > 0; o >>= 1) {
        s += __shfl_xor_sync(0xffffffffu, s, o);
        t += __shfl_xor_sync(0xffffffffu, t, o);
    }
    if (lane == 0) {
        g_fs[row] = s;
        g_fd[row] = t;
        __half r = __float2half_rn(__expf(-0.8f * s));
        g_R2[row] = h22u(__halves2half2(r, r));
        fd8[warp] = t;
    }
    __syncthreads();
    if (threadIdx.x < 4) {
        float f0 = fd8[2 * threadIdx.x], f1 = fd8[2 * threadIdx.x + 1];
        int j = blockIdx.x * 4 + threadIdx.x;
        g_B2[j] = h22u(__floats2half2_rn(__expf(f0), __expf(f1)));
        g_D2[j] = h22u(__floats2half2_rn(__expf(0.2f * f0), __expf(0.2f * f1)));
    }
}

// ---------------------------------------------------------------------------
// K2: Wh16 = X16 @ W16  via mma.sync + cp.async tiles
// ---------------------------------------------------------------------------
__global__ __launch_bounds__(256) void wh_gemm_kernel() {
    __shared__ __align__(16) __half Xs[64 * 72];
    __shared__ __align__(16) __half Wsm[64 * 264];
    const int tid = threadIdx.x;
    const int warp = tid >> 5, lane = tid & 31;
    const int wm = warp >> 2, wn = warp & 3;
    const int row0 = blockIdx.x * 64;

    float c[2][8][4];
#pragma unroll
    for (int a = 0; a < 2; a++)
#pragma unroll
        for (int b = 0; b < 8; b++)
#pragma unroll
            for (int d = 0; d < 4; d++) c[a][b][d] = 0.f;

    for (int kt = 0; kt < 4; kt++) {
#pragma unroll
        for (int i = 0; i < 2; i++) {
            int ci = i * 256 + tid;
            int r = ci >> 3, o = ci & 7;
            CP16(smem_u32(&Xs[r * 72 + o * 8]),
                 &g_X16[(size_t)(row0 + r) * DD + kt * 64 + o * 8]);
        }
#pragma unroll
        for (int i = 0; i < 8; i++) {
            int ci = i * 256 + tid;
            int r = ci >> 5, o = ci & 31;
            CP16(smem_u32(&Wsm[r * 264 + o * 8]),
                 &g_W16[(size_t)(kt * 64 + r) * DD + o * 8]);
        }
        CPCOMMIT();
        CPWAIT0();
        __syncthreads();

#pragma unroll
        for (int ks = 0; ks < 4; ks++) {
            unsigned a[2][4];
#pragma unroll
            for (int mt = 0; mt < 2; mt++)
                ldsm4(a[mt][0], a[mt][1], a[mt][2], a[mt][3],
                      smem_u32(&Xs[(wm * 32 + mt * 16 + (lane & 15)) * 72 +
                                   ks * 16 + ((lane >> 4) << 3)]));
#pragma unroll
            for (int np = 0; np < 4; np++) {
                unsigned b0, b1, b2, b3;
                ldsm4t(b0, b1, b2, b3,
                       smem_u32(&Wsm[(ks * 16 + (lane & 15)) * 264 +
                                     wn * 64 + np * 16 + ((lane >> 4) << 3)]));
#pragma unroll
                for (int mt = 0; mt < 2; mt++) {
                    mma16816(c[mt][np * 2], a[mt][0], a[mt][1], a[mt][2], a[mt][3], b0, b1);
                    mma16816(c[mt][np * 2 + 1], a[mt][0], a[mt][1], a[mt][2], a[mt][3], b2, b3);
                }
            }
        }
        __syncthreads();
    }

    const int g = lane >> 2, tq = lane & 3;
#pragma unroll
    for (int mt = 0; mt < 2; mt++)
#pragma unroll
        for (int nb = 0; nb < 8; nb++) {
            int row = row0 + wm * 32 + mt * 16 + g;
            int col = wn * 64 + nb * 8 + tq * 2;
            *(unsigned*)&g_Wh16[(size_t)row * NB + col] =
                h22u(__floats2half2_rn(c[mt][nb][0], c[mt][nb][1]));
            *(unsigned*)&g_Wh16[(size_t)(row + 8) * NB + col] =
                h22u(__floats2half2_rn(c[mt][nb][2], c[mt][nb][3]));
        }
}

// ---------------------------------------------------------------------------
// K3: warp-specialized fused attn (R13 structure, fp16 accumulators).
// 384 threads: warps 0-7 = MMA consumers (256 thr), warps 8-11 = producers.
// 64 col-tiles of 128; P ring depth 3, B ring depth 2.
// P values scaled by 1/16 (mask=0.0625) so per-tile fp16 sums stay in range;
// the scale cancels in the softmax division (l accumulates the same values).
// Per-tile fp16 accumulators promoted to fp32 once per tile.
// ---------------------------------------------------------------------------
#define PFB(s) (0 + 8 * (s))     // 3 stages
#define PEB(s) (24 + 8 * (s))
#define BFB(s) (48 + 8 * (s))    // 2 stages
#define BEB(s) (64 + 8 * (s))
#define L4O 128
#define PSO 1024
#define PS_B 17408                     // 64 * 136 halves * 2B
#define BS0O (PSO + 3 * PS_B)          // 53248
#define BS_B 67584                     // 128 * 264 halves * 2B
#define K3_SMEM (BS0O + 2 * BS_B)      // 188416
#define BTILE 67584u
#define NT (NN / 128)                  // 64 tiles

__global__ __launch_bounds__(384, 1) void attn_kernel(const int* __restrict__ adj,
                                                      float* __restrict__ out) {
    extern __shared__ __align__(128) char sm[];
    const uint32_t base = smem_u32(sm);
    float* l4 = (float*)(sm + L4O);

    const int tid = threadIdx.x;
    const int warp = tid >> 5, lane = tid & 31;
    const int row0 = blockIdx.x * 64;

    if (tid == 0) {
#pragma unroll
        for (int s = 0; s < 3; s++) {
            MBAR_INIT(base + PFB(s), 128);
            MBAR_INIT(base + PEB(s), 256);
        }
#pragma unroll
        for (int s = 0; s < 2; s++) {
            MBAR_INIT(base + BFB(s), 1);
            MBAR_INIT(base + BEB(s), 256);
        }
    }
    __syncthreads();

    if (warp >= 8) {
        // ================= PRODUCER warps (128 threads) =================
        const int ptid = tid - 256;
        const int r = ptid >> 1, h = ptid & 1;       // row, 64-col half
        const __half2 R2h = u2h2(g_R2[row0 + r]);
        const int4* arow = (const int4*)(adj + (size_t)(row0 + r) * NN);
        float lacc = 0.f;
        int be_ph0 = 0, be_ph1 = 0;

        if (ptid == 0) {
            EXPECT_TX(base + BFB(0), BTILE);
            TMA_BULK(base + BS0O, (const void*)&g_Wh16[0], BTILE, base + BFB(0));
        }

        for (int t = 0; t < NT; t++) {
            const int u = t / 3;
            const int s = t - 3 * u;
            __half* Ps = (__half*)(sm + PSO + s * PS_B);

            // TMA for tile t+1 into B stage (t+1)&1
            if (ptid == 0 && t + 1 < NT) {
                const int b2 = (t + 1) & 1;
                if (t + 1 >= 2) {
                    if (b2 == 0) { mbar_wait(base + BEB(0), be_ph0); be_ph0 ^= 1; }
                    else         { mbar_wait(base + BEB(1), be_ph1); be_ph1 ^= 1; }
                }
                EXPECT_TX(base + BFB(b2), BTILE);
                TMA_BULK(base + BS0O + b2 * BS_B,
                         (const void*)&g_Wh16[(size_t)(t + 1) * 128 * NB], BTILE,
                         base + BFB(b2));
            }

            // wait until MMA released this P stage (tile t-3 consumed)
            if (t >= 3) mbar_wait(base + PEB(s), (u - 1) & 1);

            // edge-gen: 64 cols for (r, h); mask = 0.0625 (scale p by 1/16)
            const int cb = t * 128 + h * 64;
            const int hb = cb >> 1;
            uint4 bu[8], du[8];
#pragma unroll
            for (int i = 0; i < 8; i++) {
                bu[i] = *(const uint4*)&g_B2[hb + i * 4];
                du[i] = *(const uint4*)&g_D2[hb + i * 4];
            }
            const unsigned* bb = (const unsigned*)bu;
            const unsigned* dd = (const unsigned*)du;
            int4 a4[16];
#pragma unroll
            for (int u2 = 0; u2 < 16; u2++) a4[u2] = __ldcs(&arow[cb / 4 + u2]);
#pragma unroll
            for (int u2 = 0; u2 < 16; u2++) {
                unsigned mka = (a4[u2].x > 0 ? 0x2C00u : 0u) | (a4[u2].y > 0 ? 0x2C000000u : 0u);
                unsigned mkb = (a4[u2].z > 0 ? 0x2C00u : 0u) | (a4[u2].w > 0 ? 0x2C000000u : 0u);
                __half2 pa = __hmul2(__hmax2(u2h2(bb[u2 * 2]), __hmul2(R2h, u2h2(dd[u2 * 2]))),
                                     u2h2(mka));
                __half2 pb = __hmul2(__hmax2(u2h2(bb[u2 * 2 + 1]),
                                             __hmul2(R2h, u2h2(dd[u2 * 2 + 1]))),
                                     u2h2(mkb));
                *(uint2*)&Ps[r * 136 + h * 64 + u2 * 4] = make_uint2(h22u(pa), h22u(pb));
                float2 fa = __half22float2(__hadd2(pa, pb));
                lacc += fa.x + fa.y;
            }
            MBAR_ARRIVE(base + PFB(s));
        }
        l4[r * 2 + h] = lacc;
        __syncthreads();   // join with consumers
    } else {
        // ============ MMA warps (256 threads), fp16 acc + per-tile promote ==
        const int wm = warp >> 2, wn = warp & 3;
        const int alo = lane & 15, ahi = (lane >> 4) << 3;
        int bf_ph0 = 0, bf_ph1 = 0;

        float c[2][8][4];
#pragma unroll
        for (int a = 0; a < 2; a++)
#pragma unroll
            for (int b = 0; b < 8; b++)
#pragma unroll
                for (int d = 0; d < 4; d++) c[a][b][d] = 0.f;

        for (int t = 0; t < NT; t++) {
            const int u = t / 3;
            const int s = t - 3 * u;
            const int b = t & 1;
            const __half* Ps = (const __half*)(sm + PSO + s * PS_B);
            const __half* Bs = (const __half*)(sm + BS0O + b * BS_B);

            mbar_wait(base + PFB(s), u & 1);
            if (b == 0) { mbar_wait(base + BFB(0), bf_ph0); bf_ph0 ^= 1; }
            else        { mbar_wait(base + BFB(1), bf_ph1); bf_ph1 ^= 1; }

            const uint32_t pA = smem_u32(&Ps[(wm * 32 + alo) * 136 + ahi]);
            const uint32_t pB = smem_u32(&Bs[alo * 264 + wn * 64 + ahi]);

            unsigned c16[2][8][2];
#pragma unroll
            for (int mt = 0; mt < 2; mt++)
#pragma unroll
                for (int nb = 0; nb < 8; nb++) { c16[mt][nb][0] = 0; c16[mt][nb][1] = 0; }

            unsigned acur[2][4], anxt[2][4], bcur[4], bnxt[4];
#pragma unroll
            for (int mt = 0; mt < 2; mt++)
                ldsm4(acur[mt][0], acur[mt][1], acur[mt][2], acur[mt][3],
                      pA + mt * (16 * 136 * 2));
            ldsm4t(bcur[0], bcur[1], bcur[2], bcur[3], pB);

#pragma unroll
            for (int ks = 0; ks < 8; ks++) {
#pragma unroll
                for (int np = 0; np < 4; np++) {
                    if (np < 3) {
                        ldsm4t(bnxt[0], bnxt[1], bnxt[2], bnxt[3],
                               pB + ks * (16 * 264 * 2) + (np + 1) * (16 * 2));
                    } else if (ks < 7) {
#pragma unroll
                        for (int mt = 0; mt < 2; mt++)
                            ldsm4(anxt[mt][0], anxt[mt][1], anxt[mt][2], anxt[mt][3],
                                  pA + mt * (16 * 136 * 2) + (ks + 1) * (16 * 2));
                        ldsm4t(bnxt[0], bnxt[1], bnxt[2], bnxt[3],
                               pB + (ks + 1) * (16 * 264 * 2));
                    }
#pragma unroll
                    for (int mt = 0; mt < 2; mt++) {
                        mma16816h(c16[mt][np * 2][0], c16[mt][np * 2][1],
                                  acur[mt][0], acur[mt][1], acur[mt][2], acur[mt][3],
                                  bcur[0], bcur[1]);
                        mma16816h(c16[mt][np * 2 + 1][0], c16[mt][np * 2 + 1][1],
                                  acur[mt][0], acur[mt][1], acur[mt][2], acur[mt][3],
                                  bcur[2], bcur[3]);
                    }
#pragma unroll
                    for (int i = 0; i < 4; i++) bcur[i] = bnxt[i];
                }
#pragma unroll
                for (int mt = 0; mt < 2; mt++)
#pragma unroll
                    for (int i = 0; i < 4; i++) acur[mt][i] = anxt[mt][i];
            }

            // promote tile partial (fp16) into fp32 accumulators
#pragma unroll
            for (int mt = 0; mt < 2; mt++)
#pragma unroll
                for (int nb = 0; nb < 8; nb++) {
                    float2 f0 = __half22float2(u2h2(c16[mt][nb][0]));
                    float2 f1 = __half22float2(u2h2(c16[mt][nb][1]));
                    c[mt][nb][0] += f0.x;
                    c[mt][nb][1] += f0.y;
                    c[mt][nb][2] += f1.x;
                    c[mt][nb][3] += f1.y;
                }

            MBAR_ARRIVE(base + PEB(s));
            MBAR_ARRIVE(base + BEB(b));
        }

        __syncthreads();   // l4 ready

        // ---- epilogue: normalize + elu + store ----
#pragma unroll
        for (int mt = 0; mt < 2; mt++) {
            int rl = wm * 32 + mt * 16 + (lane >> 2);
            float inv1 = 1.f / (l4[rl * 2] + l4[rl * 2 + 1]);
            float inv2 = 1.f / (l4[(rl + 8) * 2] + l4[(rl + 8) * 2 + 1]);
#pragma unroll
            for (int nb = 0; nb < 8; nb++) {
                int col = wn * 64 + nb * 8 + (lane & 3) * 2;
                float x0 = c[mt][nb][0] * inv1, x1 = c[mt][nb][1] * inv1;
                float y0 = c[mt][nb][2] * inv2, y1 = c[mt][nb][3] * inv2;
                float2 v1 = make_float2(x0 > 0.f ? x0 : expm1f(x0),
                                        x1 > 0.f ? x1 : expm1f(x1));
                float2 v2 = make_float2(y0 > 0.f ? y0 : expm1f(y0),
                                        y1 > 0.f ? y1 : expm1f(y1));
                *(float2*)&out[(size_t)(row0 + rl) * DD + col] = v1;
                *(float2*)&out[(size_t)(row0 + rl + 8) * DD + col] = v2;
            }
        }
    }
}

// ---------------------------------------------------------------------------
extern "C" void kernel_launch(void* const* d_in, const int* in_sizes, int n_in,
                              void* d_out, int out_size) {
    const float* X     = (const float*)d_in[0];
    const int*   adj   = (const int*)d_in[1];
    const float* W     = (const float*)d_in[2];
    const float* a_src = (const float*)d_in[3];
    const float* a_dst = (const float*)d_in[4];
    float* out = (float*)d_out;
    (void)in_sizes; (void)n_in; (void)out_size;

    cudaFuncSetAttribute(attn_kernel,
                         cudaFuncAttributeMaxDynamicSharedMemorySize, K3_SMEM);

    conv_xw_wvec_kernel<<<1057, 256>>>(X, W, a_src, a_dst);
    fsfd_consts_kernel<<<NN / 8, 256>>>(X);
    wh_gemm_kernel<<<NN / 64, 256>>>();
    attn_kernel<<<NN / 64, 384, K3_SMEM>>>(adj, out);
}

// round 17
// speedup vs baseline: 1.6872x; 1.1864x over previous
#include <cuda_runtime.h>
#include <cuda_fp16.h>
#include <cstdint>
#include <cstddef>

#define NN 8192
#define DD 256
#define NB 264            // 256 dims + 8 halves pad -> 528B row

// ---------------- device scratch (no runtime alloc allowed) ----------------
__device__ __align__(128) __half g_Wh16[(size_t)NN * NB];
__device__ __align__(128) __half g_X16[(size_t)NN * DD];
__device__ __align__(128) __half g_W16[DD * DD];
__device__ float g_fs[NN], g_fd[NN];
__device__ float g_ws[DD], g_wd[DD];
__device__ unsigned g_R2[NN];        // half2(R_i, R_i),  R = exp(-0.8 fs)
__device__ unsigned g_B2[NN / 2];    // half2(B_2j, B_2j+1), B = exp(fd)
__device__ unsigned g_D2[NN / 2];    // half2(D_2j, D_2j+1), D = exp(0.2 fd)

// ---------------- helpers ----------------
__device__ __forceinline__ uint32_t smem_u32(const void* p) {
    uint32_t a;
    asm("{ .reg .u64 t; cvta.to.shared.u64 t, %1; cvt.u32.u64 %0, t; }" : "=r"(a) : "l"(p));
    return a;
}
__device__ __forceinline__ __half2 u2h2(unsigned u) { return *reinterpret_cast<__half2*>(&u); }
__device__ __forceinline__ unsigned h22u(__half2 h) { return *reinterpret_cast<unsigned*>(&h); }

#define CP16(dst, src)   asm volatile("cp.async.cg.shared.global [%0], [%1], 16;" :: "r"(dst), "l"(src))
#define CPCOMMIT()       asm volatile("cp.async.commit_group;" ::: "memory")
#define CPWAIT0()        asm volatile("cp.async.wait_group 0;" ::: "memory")
#define MBAR_INIT(mb, c) asm volatile("mbarrier.init.shared.b64 [%0], %1;" :: "r"(mb), "r"(c) : "memory")
#define MBAR_ARRIVE(mb)  asm volatile("mbarrier.arrive.shared.b64 _, [%0];" :: "r"(mb) : "memory")
#define EXPECT_TX(mb, n) asm volatile("mbarrier.arrive.expect_tx.shared.b64 _, [%0], %1;" :: "r"(mb), "r"(n) : "memory")
#define TMA_BULK(dst, src, bytes, mb) \
    asm volatile("cp.async.bulk.shared::cluster.global.mbarrier::complete_tx::bytes [%0], [%1], %2, [%3];" \
                 :: "r"(dst), "l"(src), "r"(bytes), "r"(mb) : "memory")

__device__ __forceinline__ void mbar_wait(uint32_t mb, uint32_t parity) {
    uint32_t done;
    asm volatile(
        "{\n\t.reg .pred p;\n\t"
        "mbarrier.try_wait.parity.shared.b64 p, [%1], %2;\n\t"
        "selp.b32 %0, 1, 0, p;\n\t}"
        : "=r"(done) : "r"(mb), "r"(parity) : "memory");
    if (!done) {
        asm volatile(
            "{\n\t.reg .pred P1;\n\t"
            "WL_%=:\n\t"
            "mbarrier.try_wait.parity.shared.b64 P1, [%0], %1;\n\t"
            "@P1 bra.uni WD_%=;\n\t"
            "bra.uni WL_%=;\n\t"
            "WD_%=:\n\t}"
            :: "r"(mb), "r"(parity) : "memory");
    }
}

__device__ __forceinline__ void ldsm4(unsigned &r0, unsigned &r1, unsigned &r2, unsigned &r3,
                                      uint32_t addr) {
    asm volatile("ldmatrix.sync.aligned.m8n8.x4.shared.b16 {%0,%1,%2,%3}, [%4];"
                 : "=r"(r0), "=r"(r1), "=r"(r2), "=r"(r3) : "r"(addr));
}
__device__ __forceinline__ void ldsm4t(unsigned &r0, unsigned &r1, unsigned &r2, unsigned &r3,
                                       uint32_t addr) {
    asm volatile("ldmatrix.sync.aligned.m8n8.x4.trans.shared.b16 {%0,%1,%2,%3}, [%4];"
                 : "=r"(r0), "=r"(r1), "=r"(r2), "=r"(r3) : "r"(addr));
}
__device__ __forceinline__ void mma16816(float* c, unsigned a0, unsigned a1, unsigned a2,
                                         unsigned a3, unsigned b0, unsigned b1) {
    asm volatile(
        "mma.sync.aligned.m16n8k16.row.col.f32.f16.f16.f32 "
        "{%0,%1,%2,%3}, {%4,%5,%6,%7}, {%8,%9}, {%0,%1,%2,%3};"
        : "+f"(c[0]), "+f"(c[1]), "+f"(c[2]), "+f"(c[3])
        : "r"(a0), "r"(a1), "r"(a2), "r"(a3), "r"(b0), "r"(b1));
}

// ---------------------------------------------------------------------------
// K0: convert X (blocks 0..1023), W (1024..1055), wvec (block 1056)
// ---------------------------------------------------------------------------
__global__ void conv_xw_wvec_kernel(const float* __restrict__ X, const float* __restrict__ W,
                                    const float* __restrict__ a_src,
                                    const float* __restrict__ a_dst) {
    if (blockIdx.x < 1024) {
        size_t i = ((size_t)blockIdx.x * 256 + threadIdx.x) * 8;
        float4 v0 = *(const float4*)&X[i];
        float4 v1 = *(const float4*)&X[i + 4];
        uint4 o;
        o.x = h22u(__floats2half2_rn(v0.x, v0.y));
        o.y = h22u(__floats2half2_rn(v0.z, v0.w));
        o.z = h22u(__floats2half2_rn(v1.x, v1.y));
        o.w = h22u(__floats2half2_rn(v1.z, v1.w));
        *(uint4*)&g_X16[i] = o;
    } else if (blockIdx.x < 1056) {
        size_t i = ((size_t)(blockIdx.x - 1024) * 256 + threadIdx.x) * 8;
        float4 v0 = *(const float4*)&W[i];
        float4 v1 = *(const float4*)&W[i + 4];
        uint4 o;
        o.x = h22u(__floats2half2_rn(v0.x, v0.y));
        o.y = h22u(__floats2half2_rn(v0.z, v0.w));
        o.z = h22u(__floats2half2_rn(v1.x, v1.y));
        o.w = h22u(__floats2half2_rn(v1.z, v1.w));
        *(uint4*)&g_W16[i] = o;
    } else {
        int i = threadIdx.x;
        float s = 0.f, t = 0.f;
        const float4* wr = (const float4*)&W[(size_t)i * DD];
#pragma unroll 8
        for (int o = 0; o < DD / 4; o++) {
            float4 w = wr[o];
            float4 as = *(const float4*)&a_src[o * 4];
            float4 ad = *(const float4*)&a_dst[o * 4];
            s += w.x * as.x + w.y * as.y + w.z * as.z + w.w * as.w;
            t += w.x * ad.x + w.y * ad.y + w.z * ad.z + w.w * ad.w;
        }
        g_ws[i] = s;
        g_wd[i] = t;
    }
}

// ---------------------------------------------------------------------------
// K1: fs/fd (warp per row) + fused consts epilogue (R2/B2/D2)
// ---------------------------------------------------------------------------
__global__ __launch_bounds__(256) void fsfd_consts_kernel(const float* __restrict__ X) {
    __shared__ float fd8[8];
    const int warp = threadIdx.x >> 5, lane = threadIdx.x & 31;
    const int row = blockIdx.x * 8 + warp;
    const float* xr = &X[(size_t)row * DD];
    float s = 0.f, t = 0.f;
#pragma unroll
    for (int k = lane; k < DD; k += 32) {
        float x = xr[k];
        s += x * g_ws[k];
        t += x * g_wd[k];
    }
#pragma unroll
    for (int o = 16; o > 0; o >>= 1) {
        s += __shfl_xor_sync(0xffffffffu, s, o);
        t += __shfl_xor_sync(0xffffffffu, t, o);
    }
    if (lane == 0) {
        g_fs[row] = s;
        g_fd[row] = t;
        __half r = __float2half_rn(__expf(-0.8f * s));
        g_R2[row] = h22u(__halves2half2(r, r));
        fd8[warp] = t;
    }
    __syncthreads();
    if (threadIdx.x < 4) {
        float f0 = fd8[2 * threadIdx.x], f1 = fd8[2 * threadIdx.x + 1];
        int j = blockIdx.x * 4 + threadIdx.x;
        g_B2[j] = h22u(__floats2half2_rn(__expf(f0), __expf(f1)));
        g_D2[j] = h22u(__floats2half2_rn(__expf(0.2f * f0), __expf(0.2f * f1)));
    }
}

// ---------------------------------------------------------------------------
// K2: Wh16 = X16 @ W16  via mma.sync + cp.async tiles
// ---------------------------------------------------------------------------
__global__ __launch_bounds__(256) void wh_gemm_kernel() {
    __shared__ __align__(16) __half Xs[64 * 72];
    __shared__ __align__(16) __half Wsm[64 * 264];
    const int tid = threadIdx.x;
    const int warp = tid >> 5, lane = tid & 31;
    const int wm = warp >> 2, wn = warp & 3;
    const int row0 = blockIdx.x * 64;

    float c[2][8][4];
#pragma unroll
    for (int a = 0; a < 2; a++)
#pragma unroll
        for (int b = 0; b < 8; b++)
#pragma unroll
            for (int d = 0; d < 4; d++) c[a][b][d] = 0.f;

    for (int kt = 0; kt < 4; kt++) {
#pragma unroll
        for (int i = 0; i < 2; i++) {
            int ci = i * 256 + tid;
            int r = ci >> 3, o = ci & 7;
            CP16(smem_u32(&Xs[r * 72 + o * 8]),
                 &g_X16[(size_t)(row0 + r) * DD + kt * 64 + o * 8]);
        }
#pragma unroll
        for (int i = 0; i < 8; i++) {
            int ci = i * 256 + tid;
            int r = ci >> 5, o = ci & 31;
            CP16(smem_u32(&Wsm[r * 264 + o * 8]),
                 &g_W16[(size_t)(kt * 64 + r) * DD + o * 8]);
        }
        CPCOMMIT();
        CPWAIT0();
        __syncthreads();

#pragma unroll
        for (int ks = 0; ks < 4; ks++) {
            unsigned a[2][4];
#pragma unroll
            for (int mt = 0; mt < 2; mt++)
                ldsm4(a[mt][0], a[mt][1], a[mt][2], a[mt][3],
                      smem_u32(&Xs[(wm * 32 + mt * 16 + (lane & 15)) * 72 +
                                   ks * 16 + ((lane >> 4) << 3)]));
#pragma unroll
            for (int np = 0; np < 4; np++) {
                unsigned b0, b1, b2, b3;
                ldsm4t(b0, b1, b2, b3,
                       smem_u32(&Wsm[(ks * 16 + (lane & 15)) * 264 +
                                     wn * 64 + np * 16 + ((lane >> 4) << 3)]));
#pragma unroll
                for (int mt = 0; mt < 2; mt++) {
                    mma16816(c[mt][np * 2], a[mt][0], a[mt][1], a[mt][2], a[mt][3], b0, b1);
                    mma16816(c[mt][np * 2 + 1], a[mt][0], a[mt][1], a[mt][2], a[mt][3], b2, b3);
                }
            }
        }
        __syncthreads();
    }

    const int g = lane >> 2, tq = lane & 3;
#pragma unroll
    for (int mt = 0; mt < 2; mt++)
#pragma unroll
        for (int nb = 0; nb < 8; nb++) {
            int row = row0 + wm * 32 + mt * 16 + g;
            int col = wn * 64 + nb * 8 + tq * 2;
            *(unsigned*)&g_Wh16[(size_t)row * NB + col] =
                h22u(__floats2half2_rn(c[mt][nb][0], c[mt][nb][1]));
            *(unsigned*)&g_Wh16[(size_t)(row + 8) * NB + col] =
                h22u(__floats2half2_rn(c[mt][nb][2], c[mt][nb][3]));
        }
}

// ---------------------------------------------------------------------------
// K3: warp-specialized fused attn (R13 consumer, COALESCED producers).
// 384 threads: warps 0-7 = MMA consumers (256 thr), warps 8-11 = producers.
// Producer warp p owns rows p*16..p*16+15; per row, lane reads int4 at
// col = cb + lane*4  -> 512B contiguous per LDG.128 (4 lines, was 32).
// 64 col-tiles of 128; P ring depth 3, B ring depth 2.
// ---------------------------------------------------------------------------
#define PFB(s) (0 + 8 * (s))     // 3 stages
#define PEB(s) (24 + 8 * (s))
#define BFB(s) (48 + 8 * (s))    // 2 stages
#define BEB(s) (64 + 8 * (s))
#define L4O 128                       // 64 floats (one per row)
#define PSO 1024
#define PS_B 17408                     // 64 * 136 halves * 2B
#define BS0O (PSO + 3 * PS_B)          // 53248
#define BS_B 67584                     // 128 * 264 halves * 2B
#define K3_SMEM (BS0O + 2 * BS_B)      // 188416
#define BTILE 67584u
#define NT (NN / 128)                  // 64 tiles

__global__ __launch_bounds__(384, 1) void attn_kernel(const int* __restrict__ adj,
                                                      float* __restrict__ out) {
    extern __shared__ __align__(128) char sm[];
    const uint32_t base = smem_u32(sm);
    float* l4 = (float*)(sm + L4O);    // [64] row sums

    const int tid = threadIdx.x;
    const int warp = tid >> 5, lane = tid & 31;
    const int row0 = blockIdx.x * 64;

    if (tid == 0) {
#pragma unroll
        for (int s = 0; s < 3; s++) {
            MBAR_INIT(base + PFB(s), 128);
            MBAR_INIT(base + PEB(s), 256);
        }
#pragma unroll
        for (int s = 0; s < 2; s++) {
            MBAR_INIT(base + BFB(s), 1);
            MBAR_INIT(base + BEB(s), 256);
        }
    }
    __syncthreads();

    if (warp >= 8) {
        // ============ PRODUCER warps (128 threads, coalesced adj) ==========
        const int ptid = tid - 256;
        const int pw = ptid >> 5;          // producer warp 0..3
        const int pr0 = pw * 16;           // first local row of this warp
        int be_ph0 = 0, be_ph1 = 0;

        // preload R2 for the 16 owned rows
        unsigned Rr[16];
#pragma unroll
        for (int i = 0; i < 16; i++) Rr[i] = g_R2[row0 + pr0 + i];

        float lacc[16];
#pragma unroll
        for (int i = 0; i < 16; i++) lacc[i] = 0.f;

        if (ptid == 0) {
            EXPECT_TX(base + BFB(0), BTILE);
            TMA_BULK(base + BS0O, (const void*)&g_Wh16[0], BTILE, base + BFB(0));
        }

        for (int t = 0; t < NT; t++) {
            const int u = t / 3;
            const int s = t - 3 * u;
            __half* Ps = (__half*)(sm + PSO + s * PS_B);

            // TMA for tile t+1 into B stage (t+1)&1
            if (ptid == 0 && t + 1 < NT) {
                const int b2 = (t + 1) & 1;
                if (t + 1 >= 2) {
                    if (b2 == 0) { mbar_wait(base + BEB(0), be_ph0); be_ph0 ^= 1; }
                    else         { mbar_wait(base + BEB(1), be_ph1); be_ph1 ^= 1; }
                }
                EXPECT_TX(base + BFB(b2), BTILE);
                TMA_BULK(base + BS0O + b2 * BS_B,
                         (const void*)&g_Wh16[(size_t)(t + 1) * 128 * NB], BTILE,
                         base + BFB(b2));
            }

            // wait until MMA released this P stage (tile t-3 consumed)
            if (t >= 3) mbar_wait(base + PEB(s), (u - 1) & 1);

            const int cb = t * 128;
            // per-lane column constants for cols cb + lane*4 .. +3 (hoisted)
            uint2 b2v = *(const uint2*)&g_B2[(cb >> 1) + lane * 2];
            uint2 d2v = *(const uint2*)&g_D2[(cb >> 1) + lane * 2];
            const __half2 B0 = u2h2(b2v.x), B1 = u2h2(b2v.y);
            const __half2 D0 = u2h2(d2v.x), D1 = u2h2(d2v.y);

#pragma unroll
            for (int i = 0; i < 16; i++) {
                const int lr = pr0 + i;
                int4 av = __ldcs(&((const int4*)(adj + (size_t)(row0 + lr) * NN))
                                     [(cb >> 2) + lane]);
                const __half2 R = u2h2(Rr[i]);
                unsigned mka = (av.x > 0 ? 0x3C00u : 0u) | (av.y > 0 ? 0x3C000000u : 0u);
                unsigned mkb = (av.z > 0 ? 0x3C00u : 0u) | (av.w > 0 ? 0x3C000000u : 0u);
                __half2 pa = __hmul2(__hmax2(B0, __hmul2(R, D0)), u2h2(mka));
                __half2 pb = __hmul2(__hmax2(B1, __hmul2(R, D1)), u2h2(mkb));
                *(uint2*)&Ps[lr * 136 + lane * 4] = make_uint2(h22u(pa), h22u(pb));
                float2 fa = __half22float2(__hadd2(pa, pb));
                lacc[i] += fa.x + fa.y;
            }
            MBAR_ARRIVE(base + PFB(s));
        }

        // row-sum reduction: each row's partials live across the 32 lanes
#pragma unroll
        for (int i = 0; i < 16; i++) {
            float v = lacc[i];
            v += __shfl_xor_sync(0xffffffffu, v, 16);
            v += __shfl_xor_sync(0xffffffffu, v, 8);
            v += __shfl_xor_sync(0xffffffffu, v, 4);
            v += __shfl_xor_sync(0xffffffffu, v, 2);
            v += __shfl_xor_sync(0xffffffffu, v, 1);
            if (lane == 0) l4[pr0 + i] = v;
        }
        __syncthreads();   // join with consumers
    } else {
        // ================= MMA warps (256 threads), pipelined frags =========
        const int wm = warp >> 2, wn = warp & 3;
        const int alo = lane & 15, ahi = (lane >> 4) << 3;
        int bf_ph0 = 0, bf_ph1 = 0;

        float c[2][8][4];
#pragma unroll
        for (int a = 0; a < 2; a++)
#pragma unroll
            for (int b = 0; b < 8; b++)
#pragma unroll
                for (int d = 0; d < 4; d++) c[a][b][d] = 0.f;

        for (int t = 0; t < NT; t++) {
            const int u = t / 3;
            const int s = t - 3 * u;
            const int b = t & 1;
            const __half* Ps = (const __half*)(sm + PSO + s * PS_B);
            const __half* Bs = (const __half*)(sm + BS0O + b * BS_B);

            mbar_wait(base + PFB(s), u & 1);
            if (b == 0) { mbar_wait(base + BFB(0), bf_ph0); bf_ph0 ^= 1; }
            else        { mbar_wait(base + BFB(1), bf_ph1); bf_ph1 ^= 1; }

            const uint32_t pA = smem_u32(&Ps[(wm * 32 + alo) * 136 + ahi]);
            const uint32_t pB = smem_u32(&Bs[alo * 264 + wn * 64 + ahi]);

            unsigned acur[2][4], anxt[2][4], bcur[4], bnxt[4];
#pragma unroll
            for (int mt = 0; mt < 2; mt++)
                ldsm4(acur[mt][0], acur[mt][1], acur[mt][2], acur[mt][3],
                      pA + mt * (16 * 136 * 2));
            ldsm4t(bcur[0], bcur[1], bcur[2], bcur[3], pB);

#pragma unroll
            for (int ks = 0; ks < 8; ks++) {
#pragma unroll
                for (int np = 0; np < 4; np++) {
                    if (np < 3) {
                        ldsm4t(bnxt[0], bnxt[1], bnxt[2], bnxt[3],
                               pB + ks * (16 * 264 * 2) + (np + 1) * (16 * 2));
                    } else if (ks < 7) {
#pragma unroll
                        for (int mt = 0; mt < 2; mt++)
                            ldsm4(anxt[mt][0], anxt[mt][1], anxt[mt][2], anxt[mt][3],
                                  pA + mt * (16 * 136 * 2) + (ks + 1) * (16 * 2));
                        ldsm4t(bnxt[0], bnxt[1], bnxt[2], bnxt[3],
                               pB + (ks + 1) * (16 * 264 * 2));
                    }
#pragma unroll
                    for (int mt = 0; mt < 2; mt++) {
                        mma16816(c[mt][np * 2], acur[mt][0], acur[mt][1], acur[mt][2],
                                 acur[mt][3], bcur[0], bcur[1]);
                        mma16816(c[mt][np * 2 + 1], acur[mt][0], acur[mt][1], acur[mt][2],
                                 acur[mt][3], bcur[2], bcur[3]);
                    }
#pragma unroll
                    for (int i = 0; i < 4; i++) bcur[i] = bnxt[i];
                }
#pragma unroll
                for (int mt = 0; mt < 2; mt++)
#pragma unroll
                    for (int i = 0; i < 4; i++) acur[mt][i] = anxt[mt][i];
            }
            MBAR_ARRIVE(base + PEB(s));
            MBAR_ARRIVE(base + BEB(b));
        }

        __syncthreads();   // l4 ready

        // ---- epilogue: normalize + elu + store ----
#pragma unroll
        for (int mt = 0; mt < 2; mt++) {
            int rl = wm * 32 + mt * 16 + (lane >> 2);
            float inv1 = 1.f / l4[rl];
            float inv2 = 1.f / l4[rl + 8];
#pragma unroll
            for (int nb = 0; nb < 8; nb++) {
                int col = wn * 64 + nb * 8 + (lane & 3) * 2;
                float x0 = c[mt][nb][0] * inv1, x1 = c[mt][nb][1] * inv1;
                float y0 = c[mt][nb][2] * inv2, y1 = c[mt][nb][3] * inv2;
                float2 v1 = make_float2(x0 > 0.f ? x0 : expm1f(x0),
                                        x1 > 0.f ? x1 : expm1f(x1));
                float2 v2 = make_float2(y0 > 0.f ? y0 : expm1f(y0),
                                        y1 > 0.f ? y1 : expm1f(y1));
                *(float2*)&out[(size_t)(row0 + rl) * DD + col] = v1;
                *(float2*)&out[(size_t)(row0 + rl + 8) * DD + col] = v2;
            }
        }
    }
}

// ---------------------------------------------------------------------------
extern "C" void kernel_launch(void* const* d_in, const int* in_sizes, int n_in,
                              void* d_out, int out_size) {
    const float* X     = (const float*)d_in[0];
    const int*   adj   = (const int*)d_in[1];
    const float* W     = (const float*)d_in[2];
    const float* a_src = (const float*)d_in[3];
    const float* a_dst = (const float*)d_in[4];
    float* out = (float*)d_out;
    (void)in_sizes; (void)n_in; (void)out_size;

    cudaFuncSetAttribute(attn_kernel,
                         cudaFuncAttributeMaxDynamicSharedMemorySize, K3_SMEM);

    conv_xw_wvec_kernel<<<1057, 256>>>(X, W, a_src, a_dst);
    fsfd_consts_kernel<<<NN / 8, 256>>>(X);
    wh_gemm_kernel<<<NN / 64, 256>>>();
    attn_kernel<<<NN / 64, 384, K3_SMEM>>>(adj, out);
}